// round 5
// baseline (speedup 1.0000x reference)
#include <cuda_runtime.h>
#include <math.h>
#include <stdint.h>

#define D        2048
#define NEXP     64
#define BM       64
#define KC       32
#define NCHUNK   (D / KC)     // 64
#define NTHR     128
#define LG_STRIDE 66

// smem layout (bytes)
#define A_TILE   8192         // per (buf,split): 64 rows x 32 floats x 4B
#define B_TILE   8192         // per (buf,split): 64 rows x 32 floats x 4B
#define OFF_A    0
#define OFF_B    (4 * A_TILE)             // 32768
#define OFF_PSUM (OFF_B + 4 * B_TILE)     // 65536
#define OFF_S1   (OFF_PSUM + 256)
#define OFF_S2   (OFF_S1 + 512)
#define SMEM_TOTAL (OFF_S2 + 512)         // 66816

// Prototype tf32 splits, swizzled per chunk: [chunk][split][n][c]  (1 MB, L2-resident)
__device__ __align__(16) float g_pb[NCHUNK * 2 * NEXP * KC];
__device__ float g_psum[NEXP];

// ---------------- PTX helpers (baseline, no 'a' features) ----------------
__device__ __forceinline__ uint32_t cvta_s(const void* p) {
    uint32_t a;
    asm("{ .reg .u64 t; cvta.to.shared.u64 t, %1; cvt.u32.u64 %0, t; }" : "=r"(a) : "l"(p));
    return a;
}
__device__ __forceinline__ uint32_t tf32_of(float f) {
    uint32_t r;
    asm("cvt.rna.tf32.f32 %0, %1;" : "=r"(r) : "f"(f));
    return r;
}
__device__ __forceinline__ void cp16(uint32_t dst, const void* src) {
    asm volatile("cp.async.ca.shared.global [%0], [%1], 16;" :: "r"(dst), "l"(src));
}
#define CP_COMMIT() asm volatile("cp.async.commit_group;")
#define CP_WAIT0()  asm volatile("cp.async.wait_group 0;")

#define MMA(Cf, A_, B_) asm volatile( \
    "mma.sync.aligned.m16n8k8.row.col.f32.tf32.tf32.f32 " \
    "{%0,%1,%2,%3}, {%4,%5,%6,%7}, {%8,%9}, {%0,%1,%2,%3};" \
    : "+f"((Cf)[0]), "+f"((Cf)[1]), "+f"((Cf)[2]), "+f"((Cf)[3]) \
    : "r"((A_)[0]), "r"((A_)[1]), "r"((A_)[2]), "r"((A_)[3]), \
      "r"((B_)[0]), "r"((B_)[1]))

// ---------------------------------------------------------------------------
// Kernel 1: unit-normalize prototypes, tf32 2-way split, swizzled layout.
// ---------------------------------------------------------------------------
__global__ __launch_bounds__(256) void proto_prep_kernel(const float* __restrict__ p) {
    const int e = blockIdx.x;
    const int t = threadIdx.x;
    const float* row = p + (size_t)e * D;

    __shared__ float red[256];

    float ss = 0.f;
    for (int i = t; i < D; i += 256) { float v = row[i]; ss = fmaf(v, v, ss); }
    red[t] = ss;
    __syncthreads();
    for (int s = 128; s > 0; s >>= 1) { if (t < s) red[t] += red[t + s]; __syncthreads(); }
    const float inv = 1.f / fmaxf(sqrtf(red[0]), 1e-8f);
    __syncthreads();

    const int xo = 4 * (e & 7);
    float sum = 0.f;
    for (int i = t; i < D; i += 256) {
        float v = row[i] * inv;
        sum += v;
        uint32_t u1 = tf32_of(v);
        uint32_t u2 = tf32_of(v - __uint_as_float(u1));
        const int ch = i >> 5;
        const int cc = (i & 31) ^ xo;
        g_pb[(ch * 2 + 0) * (NEXP * KC) + e * KC + cc] = __uint_as_float(u1);
        g_pb[(ch * 2 + 1) * (NEXP * KC) + e * KC + cc] = __uint_as_float(u2);
    }
    red[t] = sum;
    __syncthreads();
    for (int s = 128; s > 0; s >>= 1) { if (t < s) red[t] += red[t + s]; __syncthreads(); }
    if (t == 0) g_psum[e] = red[0];
}

// ---------------------------------------------------------------------------
// Kernel 2: tf32 mma.sync router. 64 tokens/CTA, 4 warps (m16n64 each),
// 2 CTAs/SM, double-buffered smem, 3 split-products, fused LN + top-2.
// ---------------------------------------------------------------------------
__global__ __launch_bounds__(NTHR, 2) void router_kernel(
    const float* __restrict__ x,
    float* __restrict__ out_w,
    float* __restrict__ out_i,
    int write_idx)
{
    extern __shared__ __align__(16) unsigned char smem[];
    float* sA = (float*)(smem + OFF_A);
    float* sB = (float*)(smem + OFF_B);
    float* sP = (float*)(smem + OFF_PSUM);

    const int tid  = threadIdx.x;
    const int lane = tid & 31;
    const int warp = tid >> 5;
    const int tokBase = blockIdx.x * BM;

    if (tid < NEXP) sP[tid] = g_psum[tid];

    const int tok   = tid >> 1;            // 0..63 : token row this thread co-owns
    const int khalf = (tid & 1) * 16;      // 16-float half within the 32-col chunk
    const float* xrow = x + (size_t)(tokBase + tok) * D + khalf;
    const int xor4t = 4 * (tok & 7);

    const uint32_t sB_u32 = cvta_s(sB);

    float s1 = 0.f, s2 = 0.f;
    float C[8][4];
#pragma unroll
    for (int f = 0; f < 8; f++) { C[f][0] = C[f][1] = C[f][2] = C[f][3] = 0.f; }

    float4 xr[4];

    // ---- prologue: chunk 0 ----
#pragma unroll
    for (int g = 0; g < 4; g++) xr[g] = ((const float4*)xrow)[g];
    {   // B cp.async chunk 0 -> buf 0 (16 KB, 8 float4 per thread)
        const float* src = g_pb;
#pragma unroll
        for (int i = 0; i < 8; i++) {
            const int j = tid + i * NTHR;
            cp16(sB_u32 + j * 16, src + j * 4);
        }
        CP_COMMIT();
    }
    {   // convert + store A chunk 0 -> buf 0
        float* a1p = sA + 0 * (A_TILE / 4) + tok * KC;
        float* a2p = sA + 1 * (A_TILE / 4) + tok * KC;
#pragma unroll
        for (int g = 0; g < 4; g++) {
            float4 v = xr[g];
            s1 += v.x + v.y + v.z + v.w;
            s2 = fmaf(v.x, v.x, s2); s2 = fmaf(v.y, v.y, s2);
            s2 = fmaf(v.z, v.z, s2); s2 = fmaf(v.w, v.w, s2);
            uint4 u1, u2;
            u1.x = tf32_of(v.x); u2.x = tf32_of(v.x - __uint_as_float(u1.x));
            u1.y = tf32_of(v.y); u2.y = tf32_of(v.y - __uint_as_float(u1.y));
            u1.z = tf32_of(v.z); u2.z = tf32_of(v.z - __uint_as_float(u1.z));
            u1.w = tf32_of(v.w); u2.w = tf32_of(v.w - __uint_as_float(u1.w));
            const int cc = (khalf + g * 4) ^ xor4t;
            *(uint4*)(a1p + cc) = u1;
            *(uint4*)(a2p + cc) = u2;
        }
    }
    CP_WAIT0();
    __syncthreads();

    const int np = lane >> 2;       // 0..7
    const int kq = lane & 3;        // 0..3
    const int xorb = 4 * np;

    // ---- main loop ----
    for (int c = 0; c < NCHUNK; c++) {
        const int buf = c & 1, nb = buf ^ 1;

        if (c + 1 < NCHUNK) {
            // B cp.async for next chunk into other buffer
            const float* src = g_pb + (size_t)(c + 1) * 2 * (NEXP * KC);
            const uint32_t dstb = sB_u32 + nb * 2 * B_TILE;
#pragma unroll
            for (int i = 0; i < 8; i++) {
                const int j = tid + i * NTHR;
                cp16(dstb + j * 16, src + j * 4);
            }
            CP_COMMIT();
            // x LDG for next chunk (latency hidden under mma pass)
            const float4* xs = (const float4*)(xrow + (c + 1) * KC);
#pragma unroll
            for (int g = 0; g < 4; g++) xr[g] = xs[g];
        }

        // ---- mma pass on buf: per-warp m16 x n64 ----
        {
            const float* Bb0 = sB + (buf * 2 + 0) * (B_TILE / 4);
            const float* Bb1 = sB + (buf * 2 + 1) * (B_TILE / 4);
            const float* Ab0 = sA + (buf * 2 + 0) * (A_TILE / 4) + (warp * 16 + np) * KC;
            const float* Ab1 = sA + (buf * 2 + 1) * (A_TILE / 4) + (warp * 16 + np) * KC;
#pragma unroll
            for (int s = 0; s < 4; s++) {
                const int k0 = s * 8;
                const int c0 = (k0 + kq) ^ xorb;
                const int c1 = (k0 + 4 + kq) ^ xorb;
                uint32_t b[2][8][2];
#pragma unroll
                for (int nt = 0; nt < 8; nt++) {
                    const int ro = (nt * 8 + np) * KC;
                    b[0][nt][0] = __float_as_uint(Bb0[ro + c0]);
                    b[0][nt][1] = __float_as_uint(Bb0[ro + c1]);
                    b[1][nt][0] = __float_as_uint(Bb1[ro + c0]);
                    b[1][nt][1] = __float_as_uint(Bb1[ro + c1]);
                }
                const int ca0 = (k0 + kq) ^ (4 * np);   // row&7 == np for both m-rows
                const int ca1 = (k0 + 4 + kq) ^ (4 * np);
                uint32_t a[4];
                a[0] = __float_as_uint(Ab0[ca0]);
                a[1] = __float_as_uint(Ab0[8 * KC + ca0]);
                a[2] = __float_as_uint(Ab0[ca1]);
                a[3] = __float_as_uint(Ab0[8 * KC + ca1]);
#pragma unroll
                for (int nt = 0; nt < 8; nt++) {
                    MMA(C[nt], a, b[0][nt]);            // x1*p1
                    MMA(C[nt], a, b[1][nt]);            // x1*p2
                }
                a[0] = __float_as_uint(Ab1[ca0]);
                a[1] = __float_as_uint(Ab1[8 * KC + ca0]);
                a[2] = __float_as_uint(Ab1[ca1]);
                a[3] = __float_as_uint(Ab1[8 * KC + ca1]);
#pragma unroll
                for (int nt = 0; nt < 8; nt++)
                    MMA(C[nt], a, b[0][nt]);            // x2*p1
            }
        }

        if (c + 1 < NCHUNK) {
            // convert + store A for next chunk into other buffer
            float* a1p = sA + (nb * 2 + 0) * (A_TILE / 4) + tok * KC;
            float* a2p = sA + (nb * 2 + 1) * (A_TILE / 4) + tok * KC;
#pragma unroll
            for (int g = 0; g < 4; g++) {
                float4 v = xr[g];
                s1 += v.x + v.y + v.z + v.w;
                s2 = fmaf(v.x, v.x, s2); s2 = fmaf(v.y, v.y, s2);
                s2 = fmaf(v.z, v.z, s2); s2 = fmaf(v.w, v.w, s2);
                uint4 u1, u2;
                u1.x = tf32_of(v.x); u2.x = tf32_of(v.x - __uint_as_float(u1.x));
                u1.y = tf32_of(v.y); u2.y = tf32_of(v.y - __uint_as_float(u1.y));
                u1.z = tf32_of(v.z); u2.z = tf32_of(v.z - __uint_as_float(u1.z));
                u1.w = tf32_of(v.w); u2.w = tf32_of(v.w - __uint_as_float(u1.w));
                const int cc = (khalf + g * 4) ^ xor4t;
                *(uint4*)(a1p + cc) = u1;
                *(uint4*)(a2p + cc) = u2;
            }
            CP_WAIT0();
        }
        __syncthreads();
    }

    // ---- publish stats, store logits to smem (reuse A region) ----
    ((float*)(smem + OFF_S1))[tid] = s1;
    ((float*)(smem + OFF_S2))[tid] = s2;
    float* lg = (float*)smem;
#pragma unroll
    for (int nt = 0; nt < 8; nt++) {
        const int row = warp * 16 + np;
        const int col = nt * 8 + 2 * kq;
        *(float2*)(lg + row * LG_STRIDE + col)       = make_float2(C[nt][0], C[nt][1]);
        *(float2*)(lg + (row + 8) * LG_STRIDE + col) = make_float2(C[nt][2], C[nt][3]);
    }
    __syncthreads();

    // ---- epilogue: thread t < 64 = token t ----
    if (tid < BM) {
        const int mrow = tid;
        const float* s1s = (const float*)(smem + OFF_S1);
        const float* s2s = (const float*)(smem + OFF_S2);
        const float S1 = s1s[2 * mrow] + s1s[2 * mrow + 1];
        const float S2 = s2s[2 * mrow] + s2s[2 * mrow + 1];
        const float mu   = S1 * (1.f / D);
        const float var  = S2 * (1.f / D) - mu * mu;
        const float rinv = rsqrtf(var + 1e-5f) * 0.125f;   // fold 1/TEMP

        const float* lrow = lg + mrow * LG_STRIDE;
        float best1 = -1e30f, best2 = -1e30f;
        int i1 = 0, i2 = 0;
#pragma unroll 8
        for (int e = 0; e < NEXP; e++) {
            float l = (lrow[e] - mu * sP[e]) * rinv;
            if (l > best1)      { best2 = best1; i2 = i1; best1 = l; i1 = e; }
            else if (l > best2) { best2 = l; i2 = e; }
        }
        float ed = expf(best2 - best1);
        float w1 = 1.f / (1.f + ed);
        float w2 = ed / (1.f + ed);

        const int tg = tokBase + mrow;
        out_w[tg * 2 + 0] = w1;
        out_w[tg * 2 + 1] = w2;
        if (write_idx) {
            out_i[tg * 2 + 0] = (float)i1;
            out_i[tg * 2 + 1] = (float)i2;
        }
    }
}

// ---------------------------------------------------------------------------
extern "C" void kernel_launch(void* const* d_in, const int* in_sizes, int n_in,
                              void* d_out, int out_size) {
    const float* x = (const float*)d_in[0];   // [4,4096,2048] f32
    const float* p = (const float*)d_in[1];   // [64,2048] f32
    float* out = (float*)d_out;

    const int ntok = in_sizes[0] / D;         // 16384
    const int write_idx = (out_size >= 4 * ntok) ? 1 : 0;
    float* out_i = out + 2 * ntok;

    cudaFuncSetAttribute(router_kernel, cudaFuncAttributeMaxDynamicSharedMemorySize, SMEM_TOTAL);

    proto_prep_kernel<<<NEXP, 256>>>(p);
    router_kernel<<<ntok / BM, NTHR, SMEM_TOTAL>>>(x, out, out_i, write_idx);
}